// round 16
// baseline (speedup 1.0000x reference)
#include <cuda_runtime.h>
#include <math.h>

// ---------------- problem constants ----------------
constexpr int cB = 16;
constexpr int cL = 64;
constexpr int cD = 768;
constexpr int cE = 100000;
constexpr int cR = 200;
constexpr int cT = 1000000;
constexpr int cNS = 6;
constexpr int EB = cE * cB;
constexpr int NSB = (cE + 255) / 256;   // 391
constexpr int FBLK = 1563;              // follow blocks
constexpr int NWARPS = FBLK * 8;        // 12504
constexpr int ES = 268;                 // s_ebf row stride (uints)

// ---------------- scratch ----------------
__device__ __align__(16) float g_direct[EB];          // [e][16]
__device__ __align__(16) float g_enh[EB];             // [e][16]
__device__ __align__(16) float g_YY[(size_t)3 * cE * 32];  // [t][e][way*16+b]
__device__ __align__(16) float g_res2[(size_t)cE * 32];    // [e][way*16+b]
__device__ __align__(16) float g_wrall[3 * cR * 32];  // [t][r][way*16+b] = reldist*imp
__device__ float g_qem[cB * cD];
__device__ float g_cqraw[cNS * cB * cD];
__device__ float g_coef[cNS * cB];
__device__ float g_hsum[cB];
__device__ float g_m[cNS * cB];
__device__ float g_ssum[cNS * cB];
// CSR
__device__ int g_cnt[cE];
__device__ int g_ofs[cE + 1];
__device__ int g_cur[cE];
__device__ int g_bs[NSB];
__device__ __align__(16) unsigned g_pk[cT];

// ---------------- helpers ----------------
__device__ __forceinline__ void ffma2(unsigned long long& d, unsigned long long a,
                                      unsigned long long b) {
    asm("fma.rn.f32x2 %0, %1, %2, %0;" : "+l"(d) : "l"(a), "l"(b));
}
__device__ __forceinline__ void unpk2(unsigned long long v, float& lo, float& hi) {
    asm("mov.b64 {%0, %1}, %2;" : "=f"(lo), "=f"(hi) : "l"(v));
}
__device__ __forceinline__ unsigned bf2pack(float k0, float k1) {
    unsigned r;
    asm("cvt.rn.bf16x2.f32 %0, %1, %2;" : "=r"(r) : "f"(k1), "f"(k0));
    return r;
}
__device__ __forceinline__ unsigned long long bfexp(unsigned p) {
    unsigned long long r;
    asm("{\n\t"
        ".reg .b32 lo, hi;\n\t"
        "shl.b32 lo, %1, 16;\n\t"
        "and.b32 hi, %1, 0xFFFF0000;\n\t"
        "mov.b64 %0, {lo, hi};\n\t"
        "}" : "=l"(r) : "r"(p));
    return r;
}

// ---------------- K0: zero ----------------
__global__ void k0_zero() {
    int stride = gridDim.x * blockDim.x;
    int tid = blockIdx.x * blockDim.x + threadIdx.x;
    for (int i = tid; i < cE; i += stride) g_cnt[i] = 0;
    for (int i = tid; i < cNS * cB * cD; i += stride) g_cqraw[i] = 0.f;
    if (tid < cB) g_hsum[tid] = 0.f;
    if (tid < cNS * cB) { g_m[tid] = 0.f; g_ssum[tid] = 0.f; }
}

// ---------------- qem + hop fused ----------------
__global__ void k_qemhop(const float* __restrict__ qe, const float* __restrict__ mw,
                         const float* __restrict__ mb, const float* __restrict__ hw,
                         const float* __restrict__ hb) {
    int blk = blockIdx.x;
    int tid = threadIdx.x;
    if (blk < 48) {
        __shared__ float sq[cD];
        int xc = blk % 3;
        int b = blk / 3;
        for (int i = tid; i < cD; i += 256) sq[i] = qe[b * cD + i];
        __syncthreads();
        int d = xc * 256 + tid;
        float acc = mb[d];
        #pragma unroll 4
        for (int k = 0; k < cD; ++k) acc += sq[k] * mw[k * cD + d];
        g_qem[b * cD + d] = acc;
    } else {
        __shared__ float sred[3 * 256];
        int hblk = blk - 48;
        int w = hblk >> 4, b = hblk & 15;
        float a0 = 0.f, a1 = 0.f, a2 = 0.f;
        #pragma unroll
        for (int s = 0; s < 3; ++s) {
            int d = tid + s * 256;
            float q = qe[b * cD + d];
            const float* hp = hw + ((size_t)w * cD + d) * 3;
            a0 += q * hp[0]; a1 += q * hp[1]; a2 += q * hp[2];
        }
        sred[tid] = a0; sred[256 + tid] = a1; sred[512 + tid] = a2;
        __syncthreads();
        for (int off = 128; off > 0; off >>= 1) {
            if (tid < off) {
                sred[tid] += sred[tid + off];
                sred[256 + tid] += sred[256 + tid + off];
                sred[512 + tid] += sred[512 + tid + off];
            }
            __syncthreads();
        }
        if (tid == 0) {
            float v0 = sred[0] + hb[w * 3 + 0];
            float v1 = sred[256] + hb[w * 3 + 1];
            float v2 = sred[512] + hb[w * 3 + 2];
            float mx = fmaxf(v0, fmaxf(v1, v2));
            float e0 = expf(v0 - mx), e1 = expf(v1 - mx), e2 = expf(v2 - mx);
            float inv = 1.f / (e0 + e1 + e2);
            g_coef[(w * 3 + 0) * cB + b] = e0 * inv;
            g_coef[(w * 3 + 1) * cB + b] = e1 * inv;
            g_coef[(w * 3 + 2) * cB + b] = e2 * inv;
        }
    }
}

// ---------------- CSR build ----------------
__global__ void k_count(const int* __restrict__ obj) {
    int t = blockIdx.x * blockDim.x + threadIdx.x;
    if (t < cT) atomicAdd(&g_cnt[obj[t]], 1);
}
__global__ void k_scan1() {
    __shared__ int ss[256];
    int e = blockIdx.x * 256 + threadIdx.x;
    int c = (e < cE) ? g_cnt[e] : 0;
    ss[threadIdx.x] = c;
    __syncthreads();
    for (int off = 128; off > 0; off >>= 1) {
        if (threadIdx.x < off) ss[threadIdx.x] += ss[threadIdx.x + off];
        __syncthreads();
    }
    if (threadIdx.x == 0) g_bs[blockIdx.x] = ss[0];
}
__global__ void k_scan3b() {
    __shared__ int ss[256];
    __shared__ int s_pref;
    int tid = threadIdx.x;
    int acc = 0;
    for (int i = tid; i < blockIdx.x; i += 256) acc += g_bs[i];
    ss[tid] = acc;
    __syncthreads();
    for (int off = 128; off > 0; off >>= 1) {
        if (tid < off) ss[tid] += ss[tid + off];
        __syncthreads();
    }
    if (tid == 0) s_pref = ss[0];
    __syncthreads();
    int pref = s_pref;
    __syncthreads();
    int e = blockIdx.x * 256 + tid;
    int c = (e < cE) ? g_cnt[e] : 0;
    ss[tid] = c;
    __syncthreads();
    for (int off = 1; off < 256; off <<= 1) {
        int v = (tid >= off) ? ss[tid - off] : 0;
        __syncthreads();
        ss[tid] += v;
        __syncthreads();
    }
    int ofs = pref + ss[tid] - c;
    if (e < cE) { g_ofs[e] = ofs; g_cur[e] = ofs; }
    if (blockIdx.x == 0 && tid == 0) g_ofs[cE] = cT;
}
__global__ void k_fill(const int* __restrict__ subj, const int* __restrict__ rel,
                       const int* __restrict__ obj) {
    int t = blockIdx.x * blockDim.x + threadIdx.x;
    if (t >= cT) return;
    int o = obj[t];
    int p = atomicAdd(&g_cur[o], 1);
    g_pk[p] = ((unsigned)rel[t] << 17) | (unsigned)subj[t];
}

// ---------------- cqraw ----------------
__global__ void k_cq(const float* __restrict__ qe, const float* __restrict__ sw) {
    __shared__ __align__(16) float s_sq[cB * 192];
    int i = blockIdx.y;
    int kz = blockIdx.z * 192;
    int tid = threadIdx.x;
    int d = blockIdx.x * 256 + tid;
    for (int idx = tid; idx < cB * 192; idx += 256) {
        int b = idx / 192, k = idx % 192;
        s_sq[idx] = qe[b * cD + kz + k];
    }
    __syncthreads();
    float acc[16];
    #pragma unroll
    for (int b = 0; b < 16; ++b) acc[b] = 0.f;
    for (int k0 = 0; k0 < 192; k0 += 4) {
        const float* wp = sw + ((size_t)i * cD + kz + k0) * cD + d;
        float w0 = wp[0], w1 = wp[cD], w2 = wp[2 * cD], w3 = wp[3 * cD];
        #pragma unroll
        for (int b = 0; b < 16; ++b) {
            float4 q = *(const float4*)&s_sq[b * 192 + k0];
            acc[b] += q.x * w0 + q.y * w1 + q.z * w2 + q.w * w3;
        }
    }
    #pragma unroll
    for (int b = 0; b < 16; ++b)
        atomicAdd(&g_cqraw[(i * cB + b) * cD + d], acc[b]);
}

// ---------------- direct GEMM v5 ----------------
__global__ void __launch_bounds__(128, 4)
k_direct(const float* __restrict__ heads, const float* __restrict__ emb) {
    __shared__ unsigned s_ebf[8][ES];
    __shared__ __align__(16) float2 s_qp[8][16];
    __shared__ float s_hs[16];
    int tid = threadIdx.x;
    int eg = tid & 63;
    int bg = tid >> 6;
    int e0 = blockIdx.x * 256;
    if (tid < 16) s_hs[tid] = 0.f;

    unsigned long long acc[4][8];
    #pragma unroll
    for (int e = 0; e < 4; ++e)
        #pragma unroll
        for (int j = 0; j < 8; ++j) acc[e][j] = 0ull;

    for (int kc = 0; kc < cD; kc += 16) {
        __syncthreads();
        {
            int kp = tid >> 4, b = tid & 15;
            s_qp[kp][b] = *(const float2*)&g_qem[b * cD + kc + 2 * kp];
        }
        #pragma unroll
        for (int it = 0; it < 8; ++it) {
            int f = it * 128 + tid;
            int e = f >> 2, kq = f & 3;
            int ge = e0 + e;
            float4 v = make_float4(0.f, 0.f, 0.f, 0.f);
            if (ge < cE) v = *(const float4*)&emb[(size_t)ge * cD + kc + 4 * kq];
            s_ebf[2 * kq + 0][e] = bf2pack(v.x, v.y);
            s_ebf[2 * kq + 1][e] = bf2pack(v.z, v.w);
        }
        __syncthreads();
        #pragma unroll
        for (int kp = 0; kp < 8; ++kp) {
            uint4 ep = *(const uint4*)&s_ebf[kp][4 * eg];
            unsigned long long e0u = bfexp(ep.x);
            unsigned long long e1u = bfexp(ep.y);
            unsigned long long e2u = bfexp(ep.z);
            unsigned long long e3u = bfexp(ep.w);
            ulonglong2 q01 = *(const ulonglong2*)&s_qp[kp][8 * bg + 0];
            ulonglong2 q23 = *(const ulonglong2*)&s_qp[kp][8 * bg + 2];
            ulonglong2 q45 = *(const ulonglong2*)&s_qp[kp][8 * bg + 4];
            ulonglong2 q67 = *(const ulonglong2*)&s_qp[kp][8 * bg + 6];
            ffma2(acc[0][0], e0u, q01.x); ffma2(acc[0][1], e0u, q01.y);
            ffma2(acc[0][2], e0u, q23.x); ffma2(acc[0][3], e0u, q23.y);
            ffma2(acc[0][4], e0u, q45.x); ffma2(acc[0][5], e0u, q45.y);
            ffma2(acc[0][6], e0u, q67.x); ffma2(acc[0][7], e0u, q67.y);
            ffma2(acc[1][0], e1u, q01.x); ffma2(acc[1][1], e1u, q01.y);
            ffma2(acc[1][2], e1u, q23.x); ffma2(acc[1][3], e1u, q23.y);
            ffma2(acc[1][4], e1u, q45.x); ffma2(acc[1][5], e1u, q45.y);
            ffma2(acc[1][6], e1u, q67.x); ffma2(acc[1][7], e1u, q67.y);
            ffma2(acc[2][0], e2u, q01.x); ffma2(acc[2][1], e2u, q01.y);
            ffma2(acc[2][2], e2u, q23.x); ffma2(acc[2][3], e2u, q23.y);
            ffma2(acc[2][4], e2u, q45.x); ffma2(acc[2][5], e2u, q45.y);
            ffma2(acc[2][6], e2u, q67.x); ffma2(acc[2][7], e2u, q67.y);
            ffma2(acc[3][0], e3u, q01.x); ffma2(acc[3][1], e3u, q01.y);
            ffma2(acc[3][2], e3u, q23.x); ffma2(acc[3][3], e3u, q23.y);
            ffma2(acc[3][4], e3u, q45.x); ffma2(acc[3][5], e3u, q45.y);
            ffma2(acc[3][6], e3u, q67.x); ffma2(acc[3][7], e3u, q67.y);
        }
    }

    const float INVS = 0.03608439182435161f;
    float dv[4][8];
    #pragma unroll
    for (int e = 0; e < 4; ++e)
        #pragma unroll
        for (int j = 0; j < 8; ++j) {
            float lo, hi;
            unpk2(acc[e][j], lo, hi);
            float s = lo + hi;
            dv[e][j] = 1.f / (1.f + expf(-s * INVS));
        }

    int ge0 = e0 + 4 * eg;
    #pragma unroll
    for (int e = 0; e < 4; ++e) {
        if (ge0 + e < cE) {
            *(float4*)&g_direct[(size_t)(ge0 + e) * 16 + 8 * bg] =
                make_float4(dv[e][0], dv[e][1], dv[e][2], dv[e][3]);
            *(float4*)&g_direct[(size_t)(ge0 + e) * 16 + 8 * bg + 4] =
                make_float4(dv[e][4], dv[e][5], dv[e][6], dv[e][7]);
        }
    }

    float env[4][8];
    float hs[8];
    #pragma unroll
    for (int j = 0; j < 8; ++j) hs[j] = 0.f;
    bool fullv = (ge0 + 3 < cE);
    #pragma unroll
    for (int j = 0; j < 8; ++j) {
        int b = 8 * bg + j;
        float4 h;
        if (fullv) {
            h = *(const float4*)&heads[(size_t)b * cE + ge0];
        } else {
            h.x = (ge0 + 0 < cE) ? heads[(size_t)b * cE + ge0 + 0] : 0.f;
            h.y = (ge0 + 1 < cE) ? heads[(size_t)b * cE + ge0 + 1] : 0.f;
            h.z = (ge0 + 2 < cE) ? heads[(size_t)b * cE + ge0 + 2] : 0.f;
            h.w = (ge0 + 3 < cE) ? heads[(size_t)b * cE + ge0 + 3] : 0.f;
        }
        env[0][j] = h.x * (1.f + 0.3f * dv[0][j]);
        env[1][j] = h.y * (1.f + 0.3f * dv[1][j]);
        env[2][j] = h.z * (1.f + 0.3f * dv[2][j]);
        env[3][j] = h.w * (1.f + 0.3f * dv[3][j]);
        hs[j] = env[0][j] + env[1][j] + env[2][j] + env[3][j];
    }
    #pragma unroll
    for (int e = 0; e < 4; ++e) {
        if (ge0 + e < cE) {
            *(float4*)&g_enh[(size_t)(ge0 + e) * 16 + 8 * bg] =
                make_float4(env[e][0], env[e][1], env[e][2], env[e][3]);
            *(float4*)&g_enh[(size_t)(ge0 + e) * 16 + 8 * bg + 4] =
                make_float4(env[e][4], env[e][5], env[e][6], env[e][7]);
        }
    }
    const unsigned fullm = 0xffffffffu;
    #pragma unroll
    for (int j = 0; j < 8; ++j) {
        #pragma unroll
        for (int o = 16; o > 0; o >>= 1) hs[j] += __shfl_xor_sync(fullm, hs[j], o);
    }
    if ((tid & 31) == 0) {
        #pragma unroll
        for (int j = 0; j < 8; ++j) atomicAdd(&s_hs[8 * bg + j], hs[j]);
    }
    __syncthreads();
    if (tid < 16) atomicAdd(&g_hsum[tid], s_hs[tid]);
}

// ---------------- controller v3: writes unnormalized weight table ----------------
__global__ void k_ctrl(const float* __restrict__ qwh, const int* __restrict__ amask,
                       const float* __restrict__ sbv, const float* __restrict__ rw,
                       const float* __restrict__ rbv, const float* __restrict__ temp,
                       const float* __restrict__ imp) {
    __shared__ float scq[cD];
    __shared__ float sctx[cD];
    __shared__ float slog[cL];
    __shared__ float sqd[cL];
    __shared__ float srel[cR];
    __shared__ float s_scal[2];
    int i = blockIdx.x;
    int b = blockIdx.y;
    int w = i / 3;
    int t = i % 3;
    int tid = threadIdx.x;
    int lane = tid & 31, warp = tid >> 5;
    const unsigned FM = 0xffffffffu;
    float invT = 1.f / temp[0];

    for (int d = tid; d < cD; d += 256)
        scq[d] = tanhf(g_cqraw[(i * cB + b) * cD + d] + sbv[i * cD + d]);
    __syncthreads();

    for (int l = warp; l < cL; l += 8) {
        const float* row = qwh + ((size_t)b * cL + l) * cD;
        float s = 0.f;
        #pragma unroll 4
        for (int d = lane; d < cD; d += 32) s += scq[d] * row[d];
        #pragma unroll
        for (int o = 16; o > 0; o >>= 1) s += __shfl_xor_sync(FM, s, o);
        if (lane == 0) slog[l] = s * invT;
    }
    __syncthreads();
    if (warp == 0) {
        float m = fmaxf(slog[lane], slog[lane + 32]);
        #pragma unroll
        for (int o = 16; o > 0; o >>= 1) m = fmaxf(m, __shfl_xor_sync(FM, m, o));
        if (lane == 0) s_scal[0] = m;
    }
    __syncthreads();
    if (tid < cL) sqd[tid] = expf(slog[tid] - s_scal[0]);
    __syncthreads();
    if (warp == 0) {
        float e0 = sqd[lane], e1 = sqd[lane + 32];
        float m0 = (float)amask[b * cL + lane];
        float m1 = (float)amask[b * cL + lane + 32];
        float S = e0 + e1;
        float Sm = e0 * m0 + e1 * m1;
        #pragma unroll
        for (int o = 16; o > 0; o >>= 1) {
            S += __shfl_xor_sync(FM, S, o);
            Sm += __shfl_xor_sync(FM, Sm, o);
        }
        if (lane == 0) s_scal[1] = 1.f / (Sm + 1e-6f * S);
    }
    __syncthreads();
    if (tid < cL) sqd[tid] = sqd[tid] * (float)amask[b * cL + tid] * s_scal[1];
    __syncthreads();

    {
        int d0 = tid * 3;
        float c0 = 0.f, c1 = 0.f, c2 = 0.f;
        const float* base = qwh + (size_t)b * cL * cD + d0;
        #pragma unroll 4
        for (int l = 0; l < cL; ++l) {
            const float* row = base + (size_t)l * cD;
            float q = sqd[l];
            c0 += q * row[0]; c1 += q * row[1]; c2 += q * row[2];
        }
        sctx[d0] = c0; sctx[d0 + 1] = c1; sctx[d0 + 2] = c2;
    }
    __syncthreads();

    if (tid < cR) {
        const float* wp = rw + (size_t)w * cD * cR + tid;
        float a0 = 0.f, a1 = 0.f, a2 = 0.f, a3 = 0.f;
        float a4 = 0.f, a5 = 0.f, a6 = 0.f, a7 = 0.f;
        #pragma unroll 2
        for (int d = 0; d < cD; d += 8) {
            a0 += sctx[d + 0] * wp[(d + 0) * cR];
            a1 += sctx[d + 1] * wp[(d + 1) * cR];
            a2 += sctx[d + 2] * wp[(d + 2) * cR];
            a3 += sctx[d + 3] * wp[(d + 3) * cR];
            a4 += sctx[d + 4] * wp[(d + 4) * cR];
            a5 += sctx[d + 5] * wp[(d + 5) * cR];
            a6 += sctx[d + 6] * wp[(d + 6) * cR];
            a7 += sctx[d + 7] * wp[(d + 7) * cR];
        }
        srel[tid] = rbv[w * cR + tid] + (((a0 + a1) + (a2 + a3)) + ((a4 + a5) + (a6 + a7)));
    }
    __syncthreads();
    if (warp == 0) {
        float m = -1e30f;
        for (int r = lane; r < cR; r += 32) m = fmaxf(m, srel[r]);
        #pragma unroll
        for (int o = 16; o > 0; o >>= 1) m = fmaxf(m, __shfl_xor_sync(FM, m, o));
        if (lane == 0) s_scal[0] = m;
    }
    __syncthreads();
    if (tid < cR) srel[tid] = expf(srel[tid] - s_scal[0]);
    __syncthreads();
    if (warp == 0) {
        float S = 0.f;
        for (int r = lane; r < cR; r += 32) S += srel[r];
        #pragma unroll
        for (int o = 16; o > 0; o >>= 1) S += __shfl_xor_sync(FM, S, o);
        if (lane == 0) s_scal[1] = 1.f / S;
    }
    __syncthreads();
    // write unnormalized follow weight: reldist * imp  (layout [t][r][way*16+b])
    if (tid < cR)
        g_wrall[((size_t)t * cR + tid) * 32 + w * 16 + b] =
            srel[tid] * s_scal[1] * imp[tid];
}

// ---------------- follow v5: unroll 8, clip-vs-s epilogue ----------------
__global__ void __launch_bounds__(256) k_follow5(int t) {
    __shared__ float smax[8 * 32];
    int tid = threadIdx.x;
    int lane = tid & 31;
    int wlocal = tid >> 5;
    int wid = blockIdx.x * 8 + wlocal;
    int way = lane >> 4, b = lane & 15;

    const float* wr = g_wrall + (size_t)t * cR * 32;
    const float* src;
    int stride, off;
    if (t == 0) { src = g_enh;  stride = 16; off = b; }
    else        { src = g_YY + (size_t)(t - 1) * cE * 32; stride = 32; off = lane; }

    float sc = (t == 0) ? g_hsum[b] : g_ssum[(way * 3 + t - 1) * cB + b];
    float cclip = (sc > 0.f) ? sc : 1.f;
    float cinv = 1.f / cclip;

    float wmax = 0.f;
    #pragma unroll 1
    for (int i = 0; i < 8; ++i) {
        int e = wid + i * NWARPS;
        if (e >= cE) break;
        int beg = __ldg(&g_ofs[e]), end = __ldg(&g_ofs[e + 1]);
        float acc = 0.f;
        int p = beg;
        for (; p < end && (p & 3); ++p) {
            unsigned pk = __ldg(&g_pk[p]);
            int s = pk & 0x1FFFF, r = pk >> 17;
            acc += __ldg(&src[(size_t)s * stride + off]) * __ldg(&wr[r * 32 + lane]);
        }
        for (; p + 7 < end; p += 8) {
            uint4 a = *(const uint4*)&g_pk[p];
            uint4 c4 = *(const uint4*)&g_pk[p + 4];
            int s0 = a.x & 0x1FFFF, r0 = a.x >> 17;
            int s1 = a.y & 0x1FFFF, r1 = a.y >> 17;
            int s2 = a.z & 0x1FFFF, r2 = a.z >> 17;
            int s3 = a.w & 0x1FFFF, r3 = a.w >> 17;
            int s4 = c4.x & 0x1FFFF, r4 = c4.x >> 17;
            int s5 = c4.y & 0x1FFFF, r5 = c4.y >> 17;
            int s6 = c4.z & 0x1FFFF, r6 = c4.z >> 17;
            int s7 = c4.w & 0x1FFFF, r7 = c4.w >> 17;
            float v0 = __ldg(&src[(size_t)s0 * stride + off]);
            float v1 = __ldg(&src[(size_t)s1 * stride + off]);
            float v2 = __ldg(&src[(size_t)s2 * stride + off]);
            float v3 = __ldg(&src[(size_t)s3 * stride + off]);
            float v4 = __ldg(&src[(size_t)s4 * stride + off]);
            float v5 = __ldg(&src[(size_t)s5 * stride + off]);
            float v6 = __ldg(&src[(size_t)s6 * stride + off]);
            float v7 = __ldg(&src[(size_t)s7 * stride + off]);
            float w0 = __ldg(&wr[r0 * 32 + lane]);
            float w1 = __ldg(&wr[r1 * 32 + lane]);
            float w2 = __ldg(&wr[r2 * 32 + lane]);
            float w3 = __ldg(&wr[r3 * 32 + lane]);
            float w4 = __ldg(&wr[r4 * 32 + lane]);
            float w5 = __ldg(&wr[r5 * 32 + lane]);
            float w6 = __ldg(&wr[r6 * 32 + lane]);
            float w7 = __ldg(&wr[r7 * 32 + lane]);
            acc += v0 * w0; acc += v1 * w1; acc += v2 * w2; acc += v3 * w3;
            acc += v4 * w4; acc += v5 * w5; acc += v6 * w6; acc += v7 * w7;
        }
        for (; p + 3 < end; p += 4) {
            uint4 a = *(const uint4*)&g_pk[p];
            int s0 = a.x & 0x1FFFF, r0 = a.x >> 17;
            int s1 = a.y & 0x1FFFF, r1 = a.y >> 17;
            int s2 = a.z & 0x1FFFF, r2 = a.z >> 17;
            int s3 = a.w & 0x1FFFF, r3 = a.w >> 17;
            float v0 = __ldg(&src[(size_t)s0 * stride + off]);
            float v1 = __ldg(&src[(size_t)s1 * stride + off]);
            float v2 = __ldg(&src[(size_t)s2 * stride + off]);
            float v3 = __ldg(&src[(size_t)s3 * stride + off]);
            acc += v0 * __ldg(&wr[r0 * 32 + lane]);
            acc += v1 * __ldg(&wr[r1 * 32 + lane]);
            acc += v2 * __ldg(&wr[r2 * 32 + lane]);
            acc += v3 * __ldg(&wr[r3 * 32 + lane]);
        }
        for (; p < end; ++p) {
            unsigned pk = __ldg(&g_pk[p]);
            int s = pk & 0x1FFFF, r = pk >> 17;
            acc += __ldg(&src[(size_t)s * stride + off]) * __ldg(&wr[r * 32 + lane]);
        }
        // clip(acc/s, 0, 1) == min(max(acc,0), s) / s   (s>0)
        acc = fminf(fmaxf(acc, 0.f), cclip) * cinv;
        g_res2[(size_t)e * 32 + lane] = acc;
        wmax = fmaxf(wmax, acc);
    }
    smax[wlocal * 32 + lane] = wmax;
    __syncthreads();
    if (tid < 32) {
        float m = smax[tid];
        #pragma unroll
        for (int w = 1; w < 8; ++w) m = fmaxf(m, smax[w * 32 + tid]);
        atomicMax((unsigned*)&g_m[(way * 3 + t) * cB + b], __float_as_uint(m));
    }
}

// ---------------- combine ----------------
__global__ void k_combine3(int t, const float* __restrict__ range) {
    __shared__ float c1s[32], c2s[32];
    __shared__ float sb[8 * 32];
    int tid = threadIdx.x;
    if (tid < 32) {
        int way = tid >> 4, b = tid & 15;
        int j = way * 3 + t;
        float m = g_m[j * cB + b];
        if (m <= 0.f) m = 1.f;
        c1s[tid] = (t == 0 ? 1.f : 0.7f) / m;
        if (t == 0) c2s[tid] = 0.f;
        else {
            float s = g_ssum[(j - 1) * cB + b];
            c2s[tid] = 0.3f / ((s > 0.f) ? s : 1.f);
        }
    }
    __syncthreads();
    float part[32];
    #pragma unroll
    for (int k = 0; k < 32; ++k) part[k] = 0.f;

    int e = blockIdx.x * 256 + tid;
    if (e < cE) {
        float rg[16];
        #pragma unroll
        for (int b = 0; b < 16; ++b) rg[b] = range[(size_t)b * cE + e];
        const float4* rr = (const float4*)&g_res2[(size_t)e * 32];
        const float4* pv = (const float4*)&g_YY[(size_t)(t > 0 ? t - 1 : 0) * cE * 32 + (size_t)e * 32];
        float4* yo = (float4*)&g_YY[(size_t)t * cE * 32 + (size_t)e * 32];
        #pragma unroll
        for (int q = 0; q < 8; ++q) {
            float4 v = rr[q];
            float4 pr = (t > 0) ? pv[q] : make_float4(0.f, 0.f, 0.f, 0.f);
            int l0 = q * 4;
            float4 o;
            o.x = (v.x * c1s[l0 + 0] + pr.x * c2s[l0 + 0]) * rg[(l0 + 0) & 15];
            o.y = (v.y * c1s[l0 + 1] + pr.y * c2s[l0 + 1]) * rg[(l0 + 1) & 15];
            o.z = (v.z * c1s[l0 + 2] + pr.z * c2s[l0 + 2]) * rg[(l0 + 2) & 15];
            o.w = (v.w * c1s[l0 + 3] + pr.w * c2s[l0 + 3]) * rg[(l0 + 3) & 15];
            part[l0 + 0] += o.x; part[l0 + 1] += o.y;
            part[l0 + 2] += o.z; part[l0 + 3] += o.w;
            yo[q] = o;
        }
    }
    const unsigned full = 0xffffffffu;
    #pragma unroll
    for (int k = 0; k < 32; ++k) {
        part[k] += __shfl_xor_sync(full, part[k], 16);
        part[k] += __shfl_xor_sync(full, part[k], 8);
        part[k] += __shfl_xor_sync(full, part[k], 4);
        part[k] += __shfl_xor_sync(full, part[k], 2);
        part[k] += __shfl_xor_sync(full, part[k], 1);
    }
    int lane = tid & 31, wp = tid >> 5;
    if (lane == 0)
        #pragma unroll
        for (int k = 0; k < 32; ++k) sb[wp * 32 + k] = part[k];
    __syncthreads();
    if (tid < 32) {
        float s = 0.f;
        #pragma unroll
        for (int w = 0; w < 8; ++w) s += sb[w * 32 + tid];
        int way = tid >> 4, b = tid & 15;
        atomicAdd(&g_ssum[(way * 3 + t) * cB + b], s);
    }
}

// ---------------- final ----------------
__global__ void k_final3(float* __restrict__ out) {
    __shared__ float cf[96];
    int tid = threadIdx.x;
    if (tid < 96) {
        float s = g_ssum[tid];
        cf[tid] = g_coef[tid] / ((s > 0.f) ? s : 1.f);
    }
    __syncthreads();
    int e = blockIdx.x * 256 + tid;
    if (e >= cE) return;
    float o0[16], o1[16];
    #pragma unroll
    for (int k = 0; k < 16; ++k) { o0[k] = 0.f; o1[k] = 0.f; }
    #pragma unroll
    for (int t = 0; t < 3; ++t) {
        const float4* yp = (const float4*)&g_YY[(size_t)t * cE * 32 + (size_t)e * 32];
        #pragma unroll
        for (int q = 0; q < 8; ++q) {
            float4 v = yp[q];
            int l0 = q * 4;
            float* dst = (l0 < 16) ? o0 : o1;
            int jbase = ((l0 < 16) ? 0 : 3) + t;
            dst[(l0 + 0) & 15] += cf[jbase * 16 + ((l0 + 0) & 15)] * v.x;
            dst[(l0 + 1) & 15] += cf[jbase * 16 + ((l0 + 1) & 15)] * v.y;
            dst[(l0 + 2) & 15] += cf[jbase * 16 + ((l0 + 2) & 15)] * v.z;
            dst[(l0 + 3) & 15] += cf[jbase * 16 + ((l0 + 3) & 15)] * v.w;
        }
    }
    const float4* dp = (const float4*)&g_direct[(size_t)e * 16];
    #pragma unroll
    for (int q = 0; q < 4; ++q) {
        float4 d = dp[q];
        int b0 = q * 4;
        out[(size_t)(b0 + 0) * cE + e] = o0[b0 + 0] * (1.f + 0.15f * d.x) + o1[b0 + 0];
        out[(size_t)(b0 + 1) * cE + e] = o0[b0 + 1] * (1.f + 0.15f * d.y) + o1[b0 + 1];
        out[(size_t)(b0 + 2) * cE + e] = o0[b0 + 2] * (1.f + 0.15f * d.z) + o1[b0 + 2];
        out[(size_t)(b0 + 3) * cE + e] = o0[b0 + 3] * (1.f + 0.15f * d.w) + o1[b0 + 3];
    }
}

// ---------------- launcher (R14 two-stream topology) ----------------
extern "C" void kernel_launch(void* const* d_in, const int* in_sizes, int n_in,
                              void* d_out, int out_size) {
    const float* heads = (const float*)d_in[0];
    const float* qe    = (const float*)d_in[1];
    const float* qwh   = (const float*)d_in[2];
    const int*   am    = (const int*)  d_in[3];
    const float* range = (const float*)d_in[4];
    const int*   subj  = (const int*)  d_in[5];
    const int*   rel   = (const int*)  d_in[6];
    const int*   obj   = (const int*)  d_in[7];
    const float* imp   = (const float*)d_in[8];
    const float* emb   = (const float*)d_in[9];
    const float* mw    = (const float*)d_in[10];
    const float* mb    = (const float*)d_in[11];
    const float* sw    = (const float*)d_in[12];
    const float* sbv   = (const float*)d_in[13];
    const float* rw    = (const float*)d_in[14];
    const float* rbv   = (const float*)d_in[15];
    const float* hw    = (const float*)d_in[16];
    const float* hb    = (const float*)d_in[17];
    const float* temp  = (const float*)d_in[18];
    float* out = (float*)d_out;

    static cudaStream_t s1 = nullptr;
    static cudaEvent_t e1 = nullptr, e2 = nullptr;
    if (s1 == nullptr) {
        cudaStreamCreateWithFlags(&s1, cudaStreamNonBlocking);
        cudaEventCreateWithFlags(&e1, cudaEventDisableTiming);
        cudaEventCreateWithFlags(&e2, cudaEventDisableTiming);
    }

    k0_zero<<<148, 256>>>();                             // 0
    k_qemhop<<<80, 256>>>(qe, mw, mb, hw, hb);           // 1
    cudaEventRecord(e1, 0);
    cudaStreamWaitEvent(s1, e1, 0);
    k_direct<<<NSB, 128, 0, s1>>>(heads, emb);           // overlapped
    cudaEventRecord(e2, s1);

    k_cq<<<dim3(3, 6, 4), 256>>>(qe, sw);                // 2
    k_ctrl<<<dim3(6, 16), 256>>>(qwh, am, sbv, rw, rbv, temp, imp); // 3
    k_count<<<(cT + 255) / 256, 256>>>(obj);
    k_scan1<<<NSB, 256>>>();
    k_scan3b<<<NSB, 256>>>();
    k_fill<<<(cT + 255) / 256, 256>>>(subj, rel, obj);

    cudaStreamWaitEvent(0, e2, 0);                       // join direct

    for (int t = 0; t < 3; ++t) {
        k_follow5<<<FBLK, 256>>>(t);
        k_combine3<<<NSB, 256>>>(t, range);
    }
    k_final3<<<NSB, 256>>>(out);
    (void)in_sizes; (void)n_in; (void)out_size;
}

// round 17
// speedup vs baseline: 1.0587x; 1.0587x over previous
#include <cuda_runtime.h>
#include <math.h>

// ---------------- problem constants ----------------
constexpr int cB = 16;
constexpr int cL = 64;
constexpr int cD = 768;
constexpr int cE = 100000;
constexpr int cR = 200;
constexpr int cT = 1000000;
constexpr int cNS = 6;
constexpr int EB = cE * cB;
constexpr int NSB = (cE + 255) / 256;   // 391
constexpr int FBLK = 1563;              // follow blocks
constexpr int NWARPS = FBLK * 8;        // 12504
constexpr int ES = 268;                 // s_ebf row stride (uints)

// ---------------- scratch ----------------
__device__ __align__(16) float g_direct[EB];          // [e][16]
__device__ __align__(16) float g_enh[EB];             // [e][16]
__device__ __align__(16) float g_YY[(size_t)3 * cE * 32];  // [t][e][way*16+b]
__device__ __align__(16) float g_res2[(size_t)cE * 32];    // [e][way*16+b]
__device__ __align__(16) float g_wr2[cR * 32];        // [r][way*16+b]
__device__ float g_qem[cB * cD];
__device__ float g_cqraw[cNS * cB * cD];
__device__ float g_reldist[cNS * cR * cB];
__device__ float g_coef[cNS * cB];
__device__ float g_hsum[cB];
__device__ float g_m[cNS * cB];
__device__ float g_ssum[cNS * cB];
// CSR
__device__ int g_cnt[cE];
__device__ int g_ofs[cE + 1];
__device__ int g_cur[cE];
__device__ int g_bs[NSB];
__device__ __align__(16) unsigned g_pk[cT];

// ---------------- helpers ----------------
__device__ __forceinline__ void ffma2(unsigned long long& d, unsigned long long a,
                                      unsigned long long b) {
    asm("fma.rn.f32x2 %0, %1, %2, %0;" : "+l"(d) : "l"(a), "l"(b));
}
__device__ __forceinline__ void unpk2(unsigned long long v, float& lo, float& hi) {
    asm("mov.b64 {%0, %1}, %2;" : "=f"(lo), "=f"(hi) : "l"(v));
}
__device__ __forceinline__ unsigned bf2pack(float k0, float k1) {
    unsigned r;
    asm("cvt.rn.bf16x2.f32 %0, %1, %2;" : "=r"(r) : "f"(k1), "f"(k0));
    return r;
}
__device__ __forceinline__ unsigned long long bfexp(unsigned p) {
    unsigned long long r;
    asm("{\n\t"
        ".reg .b32 lo, hi;\n\t"
        "shl.b32 lo, %1, 16;\n\t"
        "and.b32 hi, %1, 0xFFFF0000;\n\t"
        "mov.b64 %0, {lo, hi};\n\t"
        "}" : "=l"(r) : "r"(p));
    return r;
}

// ---------------- K0: zero ----------------
__global__ void k0_zero() {
    int stride = gridDim.x * blockDim.x;
    int tid = blockIdx.x * blockDim.x + threadIdx.x;
    for (int i = tid; i < cE; i += stride) g_cnt[i] = 0;
    for (int i = tid; i < cNS * cB * cD; i += stride) g_cqraw[i] = 0.f;
    if (tid < cB) g_hsum[tid] = 0.f;
    if (tid < cNS * cB) { g_m[tid] = 0.f; g_ssum[tid] = 0.f; }
}

// ---------------- qem + hop fused ----------------
__global__ void k_qemhop(const float* __restrict__ qe, const float* __restrict__ mw,
                         const float* __restrict__ mb, const float* __restrict__ hw,
                         const float* __restrict__ hb) {
    int blk = blockIdx.x;
    int tid = threadIdx.x;
    if (blk < 48) {
        __shared__ float sq[cD];
        int xc = blk % 3;
        int b = blk / 3;
        for (int i = tid; i < cD; i += 256) sq[i] = qe[b * cD + i];
        __syncthreads();
        int d = xc * 256 + tid;
        float acc = mb[d];
        #pragma unroll 4
        for (int k = 0; k < cD; ++k) acc += sq[k] * mw[k * cD + d];
        g_qem[b * cD + d] = acc;
    } else {
        __shared__ float sred[3 * 256];
        int hblk = blk - 48;
        int w = hblk >> 4, b = hblk & 15;
        float a0 = 0.f, a1 = 0.f, a2 = 0.f;
        #pragma unroll
        for (int s = 0; s < 3; ++s) {
            int d = tid + s * 256;
            float q = qe[b * cD + d];
            const float* hp = hw + ((size_t)w * cD + d) * 3;
            a0 += q * hp[0]; a1 += q * hp[1]; a2 += q * hp[2];
        }
        sred[tid] = a0; sred[256 + tid] = a1; sred[512 + tid] = a2;
        __syncthreads();
        for (int off = 128; off > 0; off >>= 1) {
            if (tid < off) {
                sred[tid] += sred[tid + off];
                sred[256 + tid] += sred[256 + tid + off];
                sred[512 + tid] += sred[512 + tid + off];
            }
            __syncthreads();
        }
        if (tid == 0) {
            float v0 = sred[0] + hb[w * 3 + 0];
            float v1 = sred[256] + hb[w * 3 + 1];
            float v2 = sred[512] + hb[w * 3 + 2];
            float mx = fmaxf(v0, fmaxf(v1, v2));
            float e0 = expf(v0 - mx), e1 = expf(v1 - mx), e2 = expf(v2 - mx);
            float inv = 1.f / (e0 + e1 + e2);
            g_coef[(w * 3 + 0) * cB + b] = e0 * inv;
            g_coef[(w * 3 + 1) * cB + b] = e1 * inv;
            g_coef[(w * 3 + 2) * cB + b] = e2 * inv;
        }
    }
}

// ---------------- CSR build ----------------
__global__ void k_count(const int* __restrict__ obj) {
    int t = blockIdx.x * blockDim.x + threadIdx.x;
    if (t < cT) atomicAdd(&g_cnt[obj[t]], 1);
}
__global__ void k_scan1() {
    __shared__ int ss[256];
    int e = blockIdx.x * 256 + threadIdx.x;
    int c = (e < cE) ? g_cnt[e] : 0;
    ss[threadIdx.x] = c;
    __syncthreads();
    for (int off = 128; off > 0; off >>= 1) {
        if (threadIdx.x < off) ss[threadIdx.x] += ss[threadIdx.x + off];
        __syncthreads();
    }
    if (threadIdx.x == 0) g_bs[blockIdx.x] = ss[0];
}
__global__ void k_scan3b() {
    __shared__ int ss[256];
    __shared__ int s_pref;
    int tid = threadIdx.x;
    int acc = 0;
    for (int i = tid; i < blockIdx.x; i += 256) acc += g_bs[i];
    ss[tid] = acc;
    __syncthreads();
    for (int off = 128; off > 0; off >>= 1) {
        if (tid < off) ss[tid] += ss[tid + off];
        __syncthreads();
    }
    if (tid == 0) s_pref = ss[0];
    __syncthreads();
    int pref = s_pref;
    __syncthreads();
    int e = blockIdx.x * 256 + tid;
    int c = (e < cE) ? g_cnt[e] : 0;
    ss[tid] = c;
    __syncthreads();
    for (int off = 1; off < 256; off <<= 1) {
        int v = (tid >= off) ? ss[tid - off] : 0;
        __syncthreads();
        ss[tid] += v;
        __syncthreads();
    }
    int ofs = pref + ss[tid] - c;
    if (e < cE) { g_ofs[e] = ofs; g_cur[e] = ofs; }
    if (blockIdx.x == 0 && tid == 0) g_ofs[cE] = cT;
}
__global__ void k_fill(const int* __restrict__ subj, const int* __restrict__ rel,
                       const int* __restrict__ obj) {
    int t = blockIdx.x * blockDim.x + threadIdx.x;
    if (t >= cT) return;
    int o = obj[t];
    int p = atomicAdd(&g_cur[o], 1);
    g_pk[p] = ((unsigned)rel[t] << 17) | (unsigned)subj[t];
}

// ---------------- cqraw v2: 16 k-chunks of 48 (288 blocks) ----------------
__global__ void k_cq(const float* __restrict__ qe, const float* __restrict__ sw) {
    __shared__ __align__(16) float s_sq[cB * 48];
    int i = blockIdx.y;
    int kz = blockIdx.z * 48;
    int tid = threadIdx.x;
    int d = blockIdx.x * 256 + tid;
    for (int idx = tid; idx < cB * 48; idx += 256) {
        int b = idx / 48, k = idx % 48;
        s_sq[idx] = qe[b * cD + kz + k];
    }
    __syncthreads();
    float acc[16];
    #pragma unroll
    for (int b = 0; b < 16; ++b) acc[b] = 0.f;
    #pragma unroll 3
    for (int k0 = 0; k0 < 48; k0 += 4) {
        const float* wp = sw + ((size_t)i * cD + kz + k0) * cD + d;
        float w0 = wp[0], w1 = wp[cD], w2 = wp[2 * cD], w3 = wp[3 * cD];
        #pragma unroll
        for (int b = 0; b < 16; ++b) {
            float4 q = *(const float4*)&s_sq[b * 48 + k0];
            acc[b] += q.x * w0 + q.y * w1 + q.z * w2 + q.w * w3;
        }
    }
    #pragma unroll
    for (int b = 0; b < 16; ++b)
        atomicAdd(&g_cqraw[(i * cB + b) * cD + d], acc[b]);
}

// ---------------- direct GEMM v5 ----------------
__global__ void __launch_bounds__(128, 4)
k_direct(const float* __restrict__ heads, const float* __restrict__ emb) {
    __shared__ unsigned s_ebf[8][ES];
    __shared__ __align__(16) float2 s_qp[8][16];
    __shared__ float s_hs[16];
    int tid = threadIdx.x;
    int eg = tid & 63;
    int bg = tid >> 6;
    int e0 = blockIdx.x * 256;
    if (tid < 16) s_hs[tid] = 0.f;

    unsigned long long acc[4][8];
    #pragma unroll
    for (int e = 0; e < 4; ++e)
        #pragma unroll
        for (int j = 0; j < 8; ++j) acc[e][j] = 0ull;

    for (int kc = 0; kc < cD; kc += 16) {
        __syncthreads();
        {
            int kp = tid >> 4, b = tid & 15;
            s_qp[kp][b] = *(const float2*)&g_qem[b * cD + kc + 2 * kp];
        }
        #pragma unroll
        for (int it = 0; it < 8; ++it) {
            int f = it * 128 + tid;
            int e = f >> 2, kq = f & 3;
            int ge = e0 + e;
            float4 v = make_float4(0.f, 0.f, 0.f, 0.f);
            if (ge < cE) v = *(const float4*)&emb[(size_t)ge * cD + kc + 4 * kq];
            s_ebf[2 * kq + 0][e] = bf2pack(v.x, v.y);
            s_ebf[2 * kq + 1][e] = bf2pack(v.z, v.w);
        }
        __syncthreads();
        #pragma unroll
        for (int kp = 0; kp < 8; ++kp) {
            uint4 ep = *(const uint4*)&s_ebf[kp][4 * eg];
            unsigned long long e0u = bfexp(ep.x);
            unsigned long long e1u = bfexp(ep.y);
            unsigned long long e2u = bfexp(ep.z);
            unsigned long long e3u = bfexp(ep.w);
            ulonglong2 q01 = *(const ulonglong2*)&s_qp[kp][8 * bg + 0];
            ulonglong2 q23 = *(const ulonglong2*)&s_qp[kp][8 * bg + 2];
            ulonglong2 q45 = *(const ulonglong2*)&s_qp[kp][8 * bg + 4];
            ulonglong2 q67 = *(const ulonglong2*)&s_qp[kp][8 * bg + 6];
            ffma2(acc[0][0], e0u, q01.x); ffma2(acc[0][1], e0u, q01.y);
            ffma2(acc[0][2], e0u, q23.x); ffma2(acc[0][3], e0u, q23.y);
            ffma2(acc[0][4], e0u, q45.x); ffma2(acc[0][5], e0u, q45.y);
            ffma2(acc[0][6], e0u, q67.x); ffma2(acc[0][7], e0u, q67.y);
            ffma2(acc[1][0], e1u, q01.x); ffma2(acc[1][1], e1u, q01.y);
            ffma2(acc[1][2], e1u, q23.x); ffma2(acc[1][3], e1u, q23.y);
            ffma2(acc[1][4], e1u, q45.x); ffma2(acc[1][5], e1u, q45.y);
            ffma2(acc[1][6], e1u, q67.x); ffma2(acc[1][7], e1u, q67.y);
            ffma2(acc[2][0], e2u, q01.x); ffma2(acc[2][1], e2u, q01.y);
            ffma2(acc[2][2], e2u, q23.x); ffma2(acc[2][3], e2u, q23.y);
            ffma2(acc[2][4], e2u, q45.x); ffma2(acc[2][5], e2u, q45.y);
            ffma2(acc[2][6], e2u, q67.x); ffma2(acc[2][7], e2u, q67.y);
            ffma2(acc[3][0], e3u, q01.x); ffma2(acc[3][1], e3u, q01.y);
            ffma2(acc[3][2], e3u, q23.x); ffma2(acc[3][3], e3u, q23.y);
            ffma2(acc[3][4], e3u, q45.x); ffma2(acc[3][5], e3u, q45.y);
            ffma2(acc[3][6], e3u, q67.x); ffma2(acc[3][7], e3u, q67.y);
        }
    }

    const float INVS = 0.03608439182435161f;
    float dv[4][8];
    #pragma unroll
    for (int e = 0; e < 4; ++e)
        #pragma unroll
        for (int j = 0; j < 8; ++j) {
            float lo, hi;
            unpk2(acc[e][j], lo, hi);
            float s = lo + hi;
            dv[e][j] = 1.f / (1.f + expf(-s * INVS));
        }

    int ge0 = e0 + 4 * eg;
    #pragma unroll
    for (int e = 0; e < 4; ++e) {
        if (ge0 + e < cE) {
            *(float4*)&g_direct[(size_t)(ge0 + e) * 16 + 8 * bg] =
                make_float4(dv[e][0], dv[e][1], dv[e][2], dv[e][3]);
            *(float4*)&g_direct[(size_t)(ge0 + e) * 16 + 8 * bg + 4] =
                make_float4(dv[e][4], dv[e][5], dv[e][6], dv[e][7]);
        }
    }

    float env[4][8];
    float hs[8];
    #pragma unroll
    for (int j = 0; j < 8; ++j) hs[j] = 0.f;
    bool fullv = (ge0 + 3 < cE);
    #pragma unroll
    for (int j = 0; j < 8; ++j) {
        int b = 8 * bg + j;
        float4 h;
        if (fullv) {
            h = *(const float4*)&heads[(size_t)b * cE + ge0];
        } else {
            h.x = (ge0 + 0 < cE) ? heads[(size_t)b * cE + ge0 + 0] : 0.f;
            h.y = (ge0 + 1 < cE) ? heads[(size_t)b * cE + ge0 + 1] : 0.f;
            h.z = (ge0 + 2 < cE) ? heads[(size_t)b * cE + ge0 + 2] : 0.f;
            h.w = (ge0 + 3 < cE) ? heads[(size_t)b * cE + ge0 + 3] : 0.f;
        }
        env[0][j] = h.x * (1.f + 0.3f * dv[0][j]);
        env[1][j] = h.y * (1.f + 0.3f * dv[1][j]);
        env[2][j] = h.z * (1.f + 0.3f * dv[2][j]);
        env[3][j] = h.w * (1.f + 0.3f * dv[3][j]);
        hs[j] = env[0][j] + env[1][j] + env[2][j] + env[3][j];
    }
    #pragma unroll
    for (int e = 0; e < 4; ++e) {
        if (ge0 + e < cE) {
            *(float4*)&g_enh[(size_t)(ge0 + e) * 16 + 8 * bg] =
                make_float4(env[e][0], env[e][1], env[e][2], env[e][3]);
            *(float4*)&g_enh[(size_t)(ge0 + e) * 16 + 8 * bg + 4] =
                make_float4(env[e][4], env[e][5], env[e][6], env[e][7]);
        }
    }
    const unsigned fullm = 0xffffffffu;
    #pragma unroll
    for (int j = 0; j < 8; ++j) {
        #pragma unroll
        for (int o = 16; o > 0; o >>= 1) hs[j] += __shfl_xor_sync(fullm, hs[j], o);
    }
    if ((tid & 31) == 0) {
        #pragma unroll
        for (int j = 0; j < 8; ++j) atomicAdd(&s_hs[8 * bg + j], hs[j]);
    }
    __syncthreads();
    if (tid < 16) atomicAdd(&g_hsum[tid], s_hs[tid]);
}

// ---------------- controller v2 ----------------
__global__ void k_ctrl(const float* __restrict__ qwh, const int* __restrict__ amask,
                       const float* __restrict__ sbv, const float* __restrict__ rw,
                       const float* __restrict__ rbv, const float* __restrict__ temp) {
    __shared__ float scq[cD];
    __shared__ float sctx[cD];
    __shared__ float slog[cL];
    __shared__ float sqd[cL];
    __shared__ float srel[cR];
    __shared__ float s_scal[2];
    int i = blockIdx.x;
    int b = blockIdx.y;
    int w = i / 3;
    int tid = threadIdx.x;
    int lane = tid & 31, warp = tid >> 5;
    const unsigned FM = 0xffffffffu;
    float invT = 1.f / temp[0];

    for (int d = tid; d < cD; d += 256)
        scq[d] = tanhf(g_cqraw[(i * cB + b) * cD + d] + sbv[i * cD + d]);
    __syncthreads();

    for (int l = warp; l < cL; l += 8) {
        const float* row = qwh + ((size_t)b * cL + l) * cD;
        float s = 0.f;
        #pragma unroll 4
        for (int d = lane; d < cD; d += 32) s += scq[d] * row[d];
        #pragma unroll
        for (int o = 16; o > 0; o >>= 1) s += __shfl_xor_sync(FM, s, o);
        if (lane == 0) slog[l] = s * invT;
    }
    __syncthreads();
    if (warp == 0) {
        float m = fmaxf(slog[lane], slog[lane + 32]);
        #pragma unroll
        for (int o = 16; o > 0; o >>= 1) m = fmaxf(m, __shfl_xor_sync(FM, m, o));
        if (lane == 0) s_scal[0] = m;
    }
    __syncthreads();
    if (tid < cL) sqd[tid] = expf(slog[tid] - s_scal[0]);
    __syncthreads();
    if (warp == 0) {
        float e0 = sqd[lane], e1 = sqd[lane + 32];
        float m0 = (float)amask[b * cL + lane];
        float m1 = (float)amask[b * cL + lane + 32];
        float S = e0 + e1;
        float Sm = e0 * m0 + e1 * m1;
        #pragma unroll
        for (int o = 16; o > 0; o >>= 1) {
            S += __shfl_xor_sync(FM, S, o);
            Sm += __shfl_xor_sync(FM, Sm, o);
        }
        if (lane == 0) s_scal[1] = 1.f / (Sm + 1e-6f * S);
    }
    __syncthreads();
    if (tid < cL) sqd[tid] = sqd[tid] * (float)amask[b * cL + tid] * s_scal[1];
    __syncthreads();

    {
        int d0 = tid * 3;
        float c0 = 0.f, c1 = 0.f, c2 = 0.f;
        const float* base = qwh + (size_t)b * cL * cD + d0;
        #pragma unroll 4
        for (int l = 0; l < cL; ++l) {
            const float* row = base + (size_t)l * cD;
            float q = sqd[l];
            c0 += q * row[0]; c1 += q * row[1]; c2 += q * row[2];
        }
        sctx[d0] = c0; sctx[d0 + 1] = c1; sctx[d0 + 2] = c2;
    }
    __syncthreads();

    if (tid < cR) {
        const float* wp = rw + (size_t)w * cD * cR + tid;
        float a0 = 0.f, a1 = 0.f, a2 = 0.f, a3 = 0.f;
        float a4 = 0.f, a5 = 0.f, a6 = 0.f, a7 = 0.f;
        #pragma unroll 2
        for (int d = 0; d < cD; d += 8) {
            a0 += sctx[d + 0] * wp[(d + 0) * cR];
            a1 += sctx[d + 1] * wp[(d + 1) * cR];
            a2 += sctx[d + 2] * wp[(d + 2) * cR];
            a3 += sctx[d + 3] * wp[(d + 3) * cR];
            a4 += sctx[d + 4] * wp[(d + 4) * cR];
            a5 += sctx[d + 5] * wp[(d + 5) * cR];
            a6 += sctx[d + 6] * wp[(d + 6) * cR];
            a7 += sctx[d + 7] * wp[(d + 7) * cR];
        }
        srel[tid] = rbv[w * cR + tid] + (((a0 + a1) + (a2 + a3)) + ((a4 + a5) + (a6 + a7)));
    }
    __syncthreads();
    if (warp == 0) {
        float m = -1e30f;
        for (int r = lane; r < cR; r += 32) m = fmaxf(m, srel[r]);
        #pragma unroll
        for (int o = 16; o > 0; o >>= 1) m = fmaxf(m, __shfl_xor_sync(FM, m, o));
        if (lane == 0) s_scal[0] = m;
    }
    __syncthreads();
    if (tid < cR) srel[tid] = expf(srel[tid] - s_scal[0]);
    __syncthreads();
    if (warp == 0) {
        float S = 0.f;
        for (int r = lane; r < cR; r += 32) S += srel[r];
        #pragma unroll
        for (int o = 16; o > 0; o >>= 1) S += __shfl_xor_sync(FM, S, o);
        if (lane == 0) s_scal[1] = 1.f / S;
    }
    __syncthreads();
    if (tid < cR)
        g_reldist[((size_t)i * cR + tid) * cB + b] = srel[tid] * s_scal[1];
}

// ---------------- wr2 table ----------------
__global__ void k_wr2v(int t, const float* __restrict__ imp) {
    int idx = blockIdx.x * blockDim.x + threadIdx.x;
    if (idx >= cR * 32) return;
    int r = idx >> 5, lane = idx & 31;
    int way = lane >> 4, b = lane & 15;
    int j = way * 3 + t;
    float s = (t == 0) ? g_hsum[b] : g_ssum[(j - 1) * cB + b];
    float invs = (s > 0.f) ? 1.f / s : 1.f;
    g_wr2[idx] = g_reldist[((size_t)j * cR + r) * cB + b] * imp[r] * invs;
}

// ---------------- follow: warp-per-entity, unroll 4 (R14 proven) ----------------
__global__ void __launch_bounds__(256) k_follow3(int t) {
    __shared__ float smax[8 * 32];
    int tid = threadIdx.x;
    int lane = tid & 31;
    int wlocal = tid >> 5;
    int wid = blockIdx.x * 8 + wlocal;
    int way = lane >> 4, b = lane & 15;

    const float* src;
    int stride, off;
    if (t == 0) { src = g_enh;  stride = 16; off = b; }
    else        { src = g_YY + (size_t)(t - 1) * cE * 32; stride = 32; off = lane; }

    float wmax = 0.f;
    #pragma unroll 1
    for (int i = 0; i < 8; ++i) {
        int e = wid + i * NWARPS;
        if (e >= cE) break;
        int beg = __ldg(&g_ofs[e]), end = __ldg(&g_ofs[e + 1]);
        float acc = 0.f;
        int p = beg;
        for (; p + 3 < end; p += 4) {
            unsigned pk0 = __ldg(&g_pk[p]);
            unsigned pk1 = __ldg(&g_pk[p + 1]);
            unsigned pk2 = __ldg(&g_pk[p + 2]);
            unsigned pk3 = __ldg(&g_pk[p + 3]);
            int s0 = pk0 & 0x1FFFF, r0 = pk0 >> 17;
            int s1 = pk1 & 0x1FFFF, r1 = pk1 >> 17;
            int s2 = pk2 & 0x1FFFF, r2 = pk2 >> 17;
            int s3 = pk3 & 0x1FFFF, r3 = pk3 >> 17;
            float v0 = __ldg(&src[(size_t)s0 * stride + off]);
            float v1 = __ldg(&src[(size_t)s1 * stride + off]);
            float v2 = __ldg(&src[(size_t)s2 * stride + off]);
            float v3 = __ldg(&src[(size_t)s3 * stride + off]);
            float w0 = __ldg(&g_wr2[r0 * 32 + lane]);
            float w1 = __ldg(&g_wr2[r1 * 32 + lane]);
            float w2 = __ldg(&g_wr2[r2 * 32 + lane]);
            float w3 = __ldg(&g_wr2[r3 * 32 + lane]);
            acc += v0 * w0;
            acc += v1 * w1;
            acc += v2 * w2;
            acc += v3 * w3;
        }
        for (; p < end; ++p) {
            unsigned pk = __ldg(&g_pk[p]);
            int s = pk & 0x1FFFF, r = pk >> 17;
            acc += __ldg(&src[(size_t)s * stride + off]) * __ldg(&g_wr2[r * 32 + lane]);
        }
        acc = fminf(fmaxf(acc, 0.f), 1.f);
        g_res2[(size_t)e * 32 + lane] = acc;
        wmax = fmaxf(wmax, acc);
    }
    smax[wlocal * 32 + lane] = wmax;
    __syncthreads();
    if (tid < 32) {
        float m = smax[tid];
        #pragma unroll
        for (int w = 1; w < 8; ++w) m = fmaxf(m, smax[w * 32 + tid]);
        atomicMax((unsigned*)&g_m[(way * 3 + t) * cB + b], __float_as_uint(m));
    }
}

// ---------------- combine ----------------
__global__ void k_combine3(int t, const float* __restrict__ range) {
    __shared__ float c1s[32], c2s[32];
    __shared__ float sb[8 * 32];
    int tid = threadIdx.x;
    if (tid < 32) {
        int way = tid >> 4, b = tid & 15;
        int j = way * 3 + t;
        float m = g_m[j * cB + b];
        if (m <= 0.f) m = 1.f;
        c1s[tid] = (t == 0 ? 1.f : 0.7f) / m;
        if (t == 0) c2s[tid] = 0.f;
        else {
            float s = g_ssum[(j - 1) * cB + b];
            c2s[tid] = 0.3f / ((s > 0.f) ? s : 1.f);
        }
    }
    __syncthreads();
    float part[32];
    #pragma unroll
    for (int k = 0; k < 32; ++k) part[k] = 0.f;

    int e = blockIdx.x * 256 + tid;
    if (e < cE) {
        float rg[16];
        #pragma unroll
        for (int b = 0; b < 16; ++b) rg[b] = range[(size_t)b * cE + e];
        const float4* rr = (const float4*)&g_res2[(size_t)e * 32];
        const float4* pv = (const float4*)&g_YY[(size_t)(t > 0 ? t - 1 : 0) * cE * 32 + (size_t)e * 32];
        float4* yo = (float4*)&g_YY[(size_t)t * cE * 32 + (size_t)e * 32];
        #pragma unroll
        for (int q = 0; q < 8; ++q) {
            float4 v = rr[q];
            float4 pr = (t > 0) ? pv[q] : make_float4(0.f, 0.f, 0.f, 0.f);
            int l0 = q * 4;
            float4 o;
            o.x = (v.x * c1s[l0 + 0] + pr.x * c2s[l0 + 0]) * rg[(l0 + 0) & 15];
            o.y = (v.y * c1s[l0 + 1] + pr.y * c2s[l0 + 1]) * rg[(l0 + 1) & 15];
            o.z = (v.z * c1s[l0 + 2] + pr.z * c2s[l0 + 2]) * rg[(l0 + 2) & 15];
            o.w = (v.w * c1s[l0 + 3] + pr.w * c2s[l0 + 3]) * rg[(l0 + 3) & 15];
            part[l0 + 0] += o.x; part[l0 + 1] += o.y;
            part[l0 + 2] += o.z; part[l0 + 3] += o.w;
            yo[q] = o;
        }
    }
    const unsigned full = 0xffffffffu;
    #pragma unroll
    for (int k = 0; k < 32; ++k) {
        part[k] += __shfl_xor_sync(full, part[k], 16);
        part[k] += __shfl_xor_sync(full, part[k], 8);
        part[k] += __shfl_xor_sync(full, part[k], 4);
        part[k] += __shfl_xor_sync(full, part[k], 2);
        part[k] += __shfl_xor_sync(full, part[k], 1);
    }
    int lane = tid & 31, wp = tid >> 5;
    if (lane == 0)
        #pragma unroll
        for (int k = 0; k < 32; ++k) sb[wp * 32 + k] = part[k];
    __syncthreads();
    if (tid < 32) {
        float s = 0.f;
        #pragma unroll
        for (int w = 0; w < 8; ++w) s += sb[w * 32 + tid];
        int way = tid >> 4, b = tid & 15;
        atomicAdd(&g_ssum[(way * 3 + t) * cB + b], s);
    }
}

// ---------------- final ----------------
__global__ void k_final3(float* __restrict__ out) {
    __shared__ float cf[96];
    int tid = threadIdx.x;
    if (tid < 96) {
        float s = g_ssum[tid];
        cf[tid] = g_coef[tid] / ((s > 0.f) ? s : 1.f);
    }
    __syncthreads();
    int e = blockIdx.x * 256 + tid;
    if (e >= cE) return;
    float o0[16], o1[16];
    #pragma unroll
    for (int k = 0; k < 16; ++k) { o0[k] = 0.f; o1[k] = 0.f; }
    #pragma unroll
    for (int t = 0; t < 3; ++t) {
        const float4* yp = (const float4*)&g_YY[(size_t)t * cE * 32 + (size_t)e * 32];
        #pragma unroll
        for (int q = 0; q < 8; ++q) {
            float4 v = yp[q];
            int l0 = q * 4;
            float* dst = (l0 < 16) ? o0 : o1;
            int jbase = ((l0 < 16) ? 0 : 3) + t;
            dst[(l0 + 0) & 15] += cf[jbase * 16 + ((l0 + 0) & 15)] * v.x;
            dst[(l0 + 1) & 15] += cf[jbase * 16 + ((l0 + 1) & 15)] * v.y;
            dst[(l0 + 2) & 15] += cf[jbase * 16 + ((l0 + 2) & 15)] * v.z;
            dst[(l0 + 3) & 15] += cf[jbase * 16 + ((l0 + 3) & 15)] * v.w;
        }
    }
    const float4* dp = (const float4*)&g_direct[(size_t)e * 16];
    #pragma unroll
    for (int q = 0; q < 4; ++q) {
        float4 d = dp[q];
        int b0 = q * 4;
        out[(size_t)(b0 + 0) * cE + e] = o0[b0 + 0] * (1.f + 0.15f * d.x) + o1[b0 + 0];
        out[(size_t)(b0 + 1) * cE + e] = o0[b0 + 1] * (1.f + 0.15f * d.y) + o1[b0 + 1];
        out[(size_t)(b0 + 2) * cE + e] = o0[b0 + 2] * (1.f + 0.15f * d.z) + o1[b0 + 2];
        out[(size_t)(b0 + 3) * cE + e] = o0[b0 + 3] * (1.f + 0.15f * d.w) + o1[b0 + 3];
    }
}

// ---------------- launcher (R14 two-stream topology) ----------------
extern "C" void kernel_launch(void* const* d_in, const int* in_sizes, int n_in,
                              void* d_out, int out_size) {
    const float* heads = (const float*)d_in[0];
    const float* qe    = (const float*)d_in[1];
    const float* qwh   = (const float*)d_in[2];
    const int*   am    = (const int*)  d_in[3];
    const float* range = (const float*)d_in[4];
    const int*   subj  = (const int*)  d_in[5];
    const int*   rel   = (const int*)  d_in[6];
    const int*   obj   = (const int*)  d_in[7];
    const float* imp   = (const float*)d_in[8];
    const float* emb   = (const float*)d_in[9];
    const float* mw    = (const float*)d_in[10];
    const float* mb    = (const float*)d_in[11];
    const float* sw    = (const float*)d_in[12];
    const float* sbv   = (const float*)d_in[13];
    const float* rw    = (const float*)d_in[14];
    const float* rbv   = (const float*)d_in[15];
    const float* hw    = (const float*)d_in[16];
    const float* hb    = (const float*)d_in[17];
    const float* temp  = (const float*)d_in[18];
    float* out = (float*)d_out;

    static cudaStream_t s1 = nullptr;
    static cudaEvent_t e1 = nullptr, e2 = nullptr;
    if (s1 == nullptr) {
        cudaStreamCreateWithFlags(&s1, cudaStreamNonBlocking);
        cudaEventCreateWithFlags(&e1, cudaEventDisableTiming);
        cudaEventCreateWithFlags(&e2, cudaEventDisableTiming);
    }

    k0_zero<<<148, 256>>>();                             // 0
    k_qemhop<<<80, 256>>>(qe, mw, mb, hw, hb);           // 1
    cudaEventRecord(e1, 0);
    cudaStreamWaitEvent(s1, e1, 0);
    k_direct<<<NSB, 128, 0, s1>>>(heads, emb);           // overlapped
    cudaEventRecord(e2, s1);

    k_cq<<<dim3(3, 6, 16), 256>>>(qe, sw);               // 2 (288 blocks now)
    k_ctrl<<<dim3(6, 16), 256>>>(qwh, am, sbv, rw, rbv, temp); // 3
    k_count<<<(cT + 255) / 256, 256>>>(obj);
    k_scan1<<<NSB, 256>>>();
    k_scan3b<<<NSB, 256>>>();
    k_fill<<<(cT + 255) / 256, 256>>>(subj, rel, obj);

    cudaStreamWaitEvent(0, e2, 0);                       // join direct

    for (int t = 0; t < 3; ++t) {
        k_wr2v<<<25, 256>>>(t, imp);
        k_follow3<<<FBLK, 256>>>(t);
        k_combine3<<<NSB, 256>>>(t, range);
    }
    k_final3<<<NSB, 256>>>(out);
    (void)in_sizes; (void)n_in; (void)out_size;
}